// round 16
// baseline (speedup 1.0000x reference)
#include <cuda_runtime.h>
#include <cuda_fp16.h>
#include <cuda_bf16.h>
#include <cstdint>

#define B_ 128
#define C_ 1024
#define D_ 256
#define ROWS (B_*C_)
#define CB (C_*B_)

// ---------------- scratch ----------------
__device__ __align__(256) __half g_xn[ROWS*D_];
__device__ __align__(256) __half g_h [ROWS*D_];
__device__ __align__(256) __half g_mix[ROWS*D_];           // mix delta (no x), fp16
__device__ __align__(256) __nv_bfloat16 g_s1t[D_*B_*C_];   // spikes1 [t][b][c]
__device__ __align__(256) __nv_bfloat16 g_s2t[D_*B_*D_];   // spikes2 [t][b][o]
__device__ float g_y1 [D_*B_*D_];                          // fp32 (threshold-critical)
__device__ __align__(256) __half g_y2h[D_*B_*C_];          // fp16 (output-linear)
__device__ float g_pS[D_*D_], g_pQ[D_*D_];                 // BN1 two-stage partials
__device__ float g_S2[C_], g_Q2[C_];                       // BN2 fused stats
__device__ float g_mu1[D_], g_rs1[D_];
// pre-split weight planes (16-bit)
__device__ __align__(256) uint16_t g_w1h [D_*D_];
__device__ __align__(256) uint16_t g_w2h [D_*D_];
__device__ __align__(256) uint16_t g_cw1b[3*D_*C_];        // bf16, 3 planes (threshold-critical)
__device__ __align__(256) uint16_t g_cw2b[2*C_*D_];        // bf16, 2 planes

// ---------------- helpers ----------------
__device__ __forceinline__ uint32_t smem_u32(const void* p) {
    uint32_t a;
    asm("{ .reg .u64 t; cvta.to.shared.u64 t, %1; cvt.u32.u64 %0, t; }" : "=r"(a) : "l"(p));
    return a;
}
__device__ __forceinline__ void ldm4(uint32_t* r, uint32_t a) {
    asm volatile("ldmatrix.sync.aligned.m8n8.x4.shared.b16 {%0,%1,%2,%3}, [%4];"
        : "=r"(r[0]), "=r"(r[1]), "=r"(r[2]), "=r"(r[3]) : "r"(a));
}
template<bool BF>
__device__ __forceinline__ void mma16816(float* c, const uint32_t* a, const uint32_t* b) {
    if (BF)
        asm volatile("mma.sync.aligned.m16n8k16.row.col.f32.bf16.bf16.f32 "
            "{%0,%1,%2,%3},{%4,%5,%6,%7},{%8,%9},{%0,%1,%2,%3};"
            : "+f"(c[0]), "+f"(c[1]), "+f"(c[2]), "+f"(c[3])
            : "r"(a[0]), "r"(a[1]), "r"(a[2]), "r"(a[3]), "r"(b[0]), "r"(b[1]));
    else
        asm volatile("mma.sync.aligned.m16n8k16.row.col.f32.f16.f16.f32 "
            "{%0,%1,%2,%3},{%4,%5,%6,%7},{%8,%9},{%0,%1,%2,%3};"
            : "+f"(c[0]), "+f"(c[1]), "+f"(c[2]), "+f"(c[3])
            : "r"(a[0]), "r"(a[1]), "r"(a[2]), "r"(a[3]), "r"(b[0]), "r"(b[1]));
}
__device__ __forceinline__ int swz(int o) { return o ^ ((o >> 3) & 0x70); }
__device__ __forceinline__ void cpa16(uint32_t s, const void* g) {
    asm volatile("cp.async.cg.shared.global [%0], [%1], 16;" :: "r"(s), "l"(g));
}
#define CP_COMMIT() asm volatile("cp.async.commit_group;" ::: "memory")
#define CP_WAIT(n)  asm volatile("cp.async.wait_group %0;" :: "n"(n) : "memory")

// ---------------- GEMM core ----------------
// ID 0 (f16):  g_xn  @ w1(1 plane)  + b1, relu -> g_h (half)
// ID 1 (f16):  g_h   @ w2(1 plane)  + b2      -> g_mix (half, NO x add)
// ID 2 (bf16): s1t[z] @ cw1(3 planes) + cb1 -> g_y1[z] fp32   [stats via two-stage kernels]
// ID 3 (bf16): s2t[z] @ cw2(2 planes) + cb2 -> g_y2h[z] fp16 + fused BN2 stats (from fp32 accs)
template<int ID, int S>
__device__ __forceinline__ void gemm_core(
    int m0, int n0, int z,
    const uint16_t* __restrict__ Bw, const float* __restrict__ bias, uint8_t* smp)
{
    constexpr bool BF  = (ID >= 2);
    constexpr int K    = (ID == 2) ? 1024 : 256;
    constexpr int NBS  = (ID < 2) ? 1 : (ID == 2) ? 3 : 2;
    constexpr int NPLK = (ID < 2) ? D_*D_ : (ID == 2) ? D_*C_ : C_*D_;
    constexpr int NC   = K / 32;
    constexpr int PL   = 8192;
    constexpr int STG  = (1 + NBS) * PL;
    const uint32_t sbase = smem_u32(smp);

    const int tid = threadIdx.x, lane = tid & 31, wid = tid >> 5;
    const int wm = wid >> 1, wn = wid & 1;
    const int lr = lane & 15, lc = (lane >> 4) << 4;

    const uint16_t* A =
        (ID == 0) ? (const uint16_t*)g_xn + (size_t)m0 * K :
        (ID == 1) ? (const uint16_t*)g_h  + (size_t)m0 * K :
        (ID == 2) ? (const uint16_t*)g_s1t + (size_t)z * (B_ * C_) :
                    (const uint16_t*)g_s2t + (size_t)z * (B_ * D_);

    const int sr = tid >> 1;
    const int sc = (tid & 1) * 16;
    const int raw = sr * 64 + sc * 2;
    const int o0 = swz(raw), o1 = swz(raw + 16);
    float acc[2][8][4] = {};

    auto ISSUE = [&](int ch) {
        const uint32_t st = sbase + (ch % S) * STG;
        const uint16_t* ap = A + (size_t)sr * K + ch * 32 + sc;
        cpa16(st + o0, ap);
        cpa16(st + o1, ap + 8);
        #pragma unroll
        for (int s = 0; s < NBS; s++) {
            const uint16_t* bp = Bw + (size_t)s * NPLK + (size_t)(n0 + sr) * K + ch * 32 + sc;
            cpa16(st + (1 + s) * PL + o0, bp);
            cpa16(st + (1 + s) * PL + o1, bp + 8);
        }
    };
    auto MMA = [&](int buf) {
        const uint32_t bs = sbase + buf * STG;
        #pragma unroll
        for (int ks = 0; ks < 2; ks++) {
            uint32_t a[2][4];
            #pragma unroll
            for (int mi = 0; mi < 2; mi++) {
                int r = (wm * 32 + mi * 16 + lr) * 64 + ks * 32 + lc;
                ldm4(a[mi], bs + swz(r));
            }
            #pragma unroll
            for (int p = 0; p < NBS; p++) {
                const uint32_t Bb = bs + (1 + p) * PL;
                uint32_t bq[8][2];
                #pragma unroll
                for (int nj = 0; nj < 4; nj++) {
                    int r = (wn * 64 + nj * 16 + lr) * 64 + ks * 32 + lc;
                    uint32_t tq[4];
                    ldm4(tq, Bb + swz(r));
                    bq[2*nj][0] = tq[0];   bq[2*nj][1] = tq[2];
                    bq[2*nj+1][0] = tq[1]; bq[2*nj+1][1] = tq[3];
                }
                #pragma unroll
                for (int mi = 0; mi < 2; mi++)
                    #pragma unroll
                    for (int nj = 0; nj < 8; nj++)
                        mma16816<BF>(acc[mi][nj], a[mi], bq[nj]);
            }
        }
    };

    #pragma unroll
    for (int s = 0; s < S - 1; s++) { ISSUE(s); CP_COMMIT(); }
    for (int i = 0; i < NC; i++) {
        CP_WAIT(S - 2);
        __syncthreads();
        int nx = i + S - 1;
        if (nx < NC) ISSUE(nx);
        CP_COMMIT();
        MMA(i % S);
    }

    const int er = lane >> 2, ec = (lane & 3) * 2;
    #pragma unroll
    for (int mi = 0; mi < 2; mi++) {
        #pragma unroll
        for (int nj = 0; nj < 8; nj++) {
            float* c = acc[mi][nj];
            int m = m0 + wm * 32 + mi * 16 + er;
            int n = n0 + wn * 64 + nj * 8 + ec;
            float b0 = __ldg(bias + n), b1 = __ldg(bias + n + 1);
            if (ID == 0) {
                *(__half2*)(g_h + (size_t)m * 256 + n) =
                    __floats2half2_rn(fmaxf(c[0] + b0, 0.f), fmaxf(c[1] + b1, 0.f));
                *(__half2*)(g_h + (size_t)(m + 8) * 256 + n) =
                    __floats2half2_rn(fmaxf(c[2] + b0, 0.f), fmaxf(c[3] + b1, 0.f));
            } else if (ID == 1) {
                *(__half2*)(g_mix + (size_t)m * 256 + n) =
                    __floats2half2_rn(c[0] + b0, c[1] + b1);
                *(__half2*)(g_mix + (size_t)(m + 8) * 256 + n) =
                    __floats2half2_rn(c[2] + b0, c[3] + b1);
            } else if (ID == 2) {
                float* yb = g_y1 + (size_t)z * (B_ * 256);
                *(float2*)(yb + (size_t)m * 256 + n) = make_float2(c[0] + b0, c[1] + b1);
                *(float2*)(yb + (size_t)(m + 8) * 256 + n) = make_float2(c[2] + b0, c[3] + b1);
            } else {
                float y00 = c[0] + b0, y01 = c[1] + b1;
                float y10 = c[2] + b0, y11 = c[3] + b1;
                __half* yb = g_y2h + (size_t)z * (B_ * 1024);
                *(__half2*)(yb + (size_t)m * 1024 + n) = __floats2half2_rn(y00, y01);
                *(__half2*)(yb + (size_t)(m + 8) * 1024 + n) = __floats2half2_rn(y10, y11);
                float a0 = y00 + y10, a1 = y01 + y11;
                float q0 = y00 * y00 + y10 * y10, q1 = y01 * y01 + y11 * y11;
                #pragma unroll
                for (int off = 4; off < 32; off <<= 1) {
                    a0 += __shfl_xor_sync(0xffffffffu, a0, off);
                    a1 += __shfl_xor_sync(0xffffffffu, a1, off);
                    q0 += __shfl_xor_sync(0xffffffffu, q0, off);
                    q1 += __shfl_xor_sync(0xffffffffu, q1, off);
                }
                if (er == 0) {
                    atomicAdd(g_S2 + n, a0);
                    atomicAdd(g_S2 + n + 1, a1);
                    atomicAdd(g_Q2 + n, q0);
                    atomicAdd(g_Q2 + n + 1, q1);
                }
            }
        }
    }
}

// ---------------- dual GEMM launch (grid union, heavy spike side first) ----------------
template<int IDA, int SA, int IDB, int SB, int NBA>
__global__ void __launch_bounds__(256, 2)
gemm_dual(const uint16_t* __restrict__ BwA, const float* __restrict__ biasA,
          const uint16_t* __restrict__ BwB, const float* __restrict__ biasB)
{
    extern __shared__ uint8_t smp[];
    int lb = blockIdx.x;
    if (lb < NBA) {
        int by = (IDA == 2) ? (lb & 1) : (lb & 7);
        int bz = (IDA == 2) ? (lb >> 1) : (lb >> 3);
        gemm_core<IDA, SA>(0, by * 128, bz, BwA, biasA, smp);
    } else {
        int l2 = lb - NBA;
        gemm_core<IDB, SB>((l2 & 1023) * 128, (l2 >> 10) * 128, 0, BwB, biasB, smp);
    }
}

// ---------------- front union: fused LN+LIF1 (512 blocks) + weight splits + stat zero ----------------
__device__ __forceinline__ void split_body(const float* src, uint16_t* dst, int n, int i, bool bf, int nbs) {
    if (i >= n) return;
    float v = src[i];
    for (int s = 0; s < nbs; s++) {
        if (bf) {
            __nv_bfloat16 b = __float2bfloat16(v);
            dst[s * n + i] = __bfloat16_as_ushort(b);
            v -= __bfloat162float(b);
        } else {
            __half b = __float2half_rn(v);
            dst[s * n + i] = __half_as_ushort(b);
            v -= __half2float(b);
        }
    }
}
__global__ void front_union(const float* __restrict__ x,
                            const float* __restrict__ gam, const float* __restrict__ bet,
                            const float* w1, const float* w2,
                            const float* cw1, const float* cw2) {
    if (blockIdx.x < 512) {
        // fused LIF1 + LayerNorm, thread per (b,c) row
        int tid = blockIdx.x * 256 + threadIdx.x;
        int b = tid >> 10, c = tid & 1023;
        const float4* xr = (const float4*)(x + ((size_t)b * C_ + c) * D_);
        __nv_bfloat16* sp = g_s1t + (size_t)b * C_ + c;
        float v = 0.0f, s = 0.0f, q = 0.0f;
        for (int qq = 0; qq < 64; qq++) {
            float4 xv = xr[qq];
            float xa[4] = {xv.x, xv.y, xv.z, xv.w};
            #pragma unroll
            for (int j = 0; j < 4; j++) {
                s += xa[j];
                q += xa[j] * xa[j];
                v = v + (xa[j] - v) * 0.5f;               // bit-identical LIF chain
                float sv = (v >= 1.0f) ? 1.0f : 0.0f;
                sp[(size_t)(qq * 4 + j) * CB] = __float2bfloat16(sv);
                if (v >= 1.0f) v = 0.0f;
            }
        }
        float mu = s * (1.0f / D_);
        float rs = rsqrtf(q * (1.0f / D_) - mu * mu + 1e-5f);
        __half* xo = g_xn + (size_t)tid * D_;
        for (int qq = 0; qq < 64; qq++) {
            float4 xv = xr[qq];                           // L1-resident re-read
            int t = qq * 4;
            __half2 h0 = __floats2half2_rn((xv.x - mu) * rs * __ldg(gam + t)     + __ldg(bet + t),
                                           (xv.y - mu) * rs * __ldg(gam + t + 1) + __ldg(bet + t + 1));
            __half2 h1 = __floats2half2_rn((xv.z - mu) * rs * __ldg(gam + t + 2) + __ldg(bet + t + 2),
                                           (xv.w - mu) * rs * __ldg(gam + t + 3) + __ldg(bet + t + 3));
            uint2 pk;
            pk.x = *(uint32_t*)&h0;
            pk.y = *(uint32_t*)&h1;
            *(uint2*)(xo + t) = pk;
        }
    } else {
        int bx = blockIdx.x - 512, tid = threadIdx.x;
        if (bx < 256)        split_body(w1,  g_w1h,  D_*D_, bx * 256 + tid, false, 1);
        else if (bx < 512)   split_body(w2,  g_w2h,  D_*D_, (bx - 256) * 256 + tid, false, 1);
        else if (bx < 1536)  split_body(cw1, g_cw1b, D_*C_, (bx - 512) * 256 + tid, true, 3);
        else if (bx < 2560)  split_body(cw2, g_cw2b, C_*D_, (bx - 1536) * 256 + tid, true, 2);
        else {
            int i = (bx - 2560) * 256 + tid;
            if (i < C_) { g_S2[i] = 0.f; g_Q2[i] = 0.f; }
        }
    }
}

// ---------------- BN1 two-stage stats (proven, threshold-critical) ----------------
__global__ void bn_slab1() {
    int t = blockIdx.x, tid = threadIdx.x;
    float s = 0.0f, q = 0.0f;
    const float* base = g_y1 + (size_t)t * 128 * 256;
    for (int b = 0; b < 128; b++) {
        float v = base[(size_t)b * 256 + tid];
        s += v; q += v * v;
    }
    g_pS[(size_t)t * 256 + tid] = s;
    g_pQ[(size_t)t * 256 + tid] = q;
}
__global__ void bn_reduce1() {
    int c = blockIdx.x * 256 + threadIdx.x;
    float S = 0.0f, Q = 0.0f;
    for (int t = 0; t < 256; t++) {
        S += g_pS[(size_t)t * 256 + c];
        Q += g_pQ[(size_t)t * 256 + c];
    }
    float mean = S * (1.0f / 32768.0f);
    float var = Q * (1.0f / 32768.0f) - mean * mean;
    g_mu1[c] = mean;
    g_rs1[c] = rsqrtf(var + 1e-5f);
}

// ---------------- BN1 + LIF 2 ----------------
__global__ void lif2_kernel(const float* __restrict__ gam, const float* __restrict__ bet) {
    int tid = blockIdx.x * blockDim.x + threadIdx.x;
    int b = tid >> 8, o = tid & 255;
    float mu = g_mu1[o], rs = g_rs1[o], ga = gam[o], be = bet[o];
    const float* yp = g_y1 + (size_t)b * 256 + o;
    __nv_bfloat16* sp = g_s2t + (size_t)b * 256 + o;
    float v = 0.0f;
    for (int t = 0; t < D_; t++) {
        float yn = ((yp[(size_t)t * 32768] - mu) * rs) * ga + be;
        v = v + (yn - v) * 0.5f;
        float s = (v >= 1.0f) ? 1.0f : 0.0f;
        sp[(size_t)t * 32768] = __float2bfloat16(s);
        if (v >= 1.0f) v = 0.0f;
    }
}

// ---------------- final: out = x + mix + BN2(y2) ----------------
__global__ void final_kernel(float* __restrict__ out, const float* __restrict__ x,
                             const float* __restrict__ gam, const float* __restrict__ bet) {
    __shared__ float tile[32][33];
    int b = blockIdx.x;
    int c0 = blockIdx.y << 5, t0 = blockIdx.z << 5;
    #pragma unroll
    for (int i = 0; i < 4; i++) {
        int t = t0 + threadIdx.y + i * 8;
        tile[threadIdx.y + i * 8][threadIdx.x] =
            __half2float(g_y2h[(size_t)t * (B_ * 1024) + (size_t)b * 1024 + c0 + threadIdx.x]);
    }
    __syncthreads();
    #pragma unroll
    for (int i = 0; i < 4; i++) {
        int c = c0 + threadIdx.y + i * 8;
        float mu = g_S2[c] * (1.0f / 32768.0f);
        float rs = rsqrtf(g_Q2[c] * (1.0f / 32768.0f) - mu * mu + 1e-5f);
        float ga = __ldg(gam + c), be = __ldg(bet + c);
        size_t o = (size_t)b * (C_ * D_) + (size_t)c * D_ + t0 + threadIdx.x;
        float mixv = __half2float(g_mix[o]);
        out[o] = x[o] + mixv + (tile[threadIdx.x][threadIdx.y + i * 8] - mu) * rs * ga + be;
    }
}

// ---------------- launch ----------------
extern "C" void kernel_launch(void* const* d_in, const int* in_sizes, int n_in,
                              void* d_out, int out_size) {
    const float* x    = (const float*)d_in[0];
    const float* ln_g = (const float*)d_in[1];
    const float* ln_b = (const float*)d_in[2];
    const float* w1   = (const float*)d_in[3];
    const float* b1   = (const float*)d_in[4];
    const float* w2   = (const float*)d_in[5];
    const float* b2   = (const float*)d_in[6];
    const float* cw1  = (const float*)d_in[7];
    const float* cb1  = (const float*)d_in[8];
    const float* bn1g = (const float*)d_in[9];
    const float* bn1b = (const float*)d_in[10];
    const float* cw2  = (const float*)d_in[11];
    const float* cb2  = (const float*)d_in[12];
    const float* bn2g = (const float*)d_in[13];
    const float* bn2b = (const float*)d_in[14];
    float* out = (float*)d_out;
    (void)in_sizes; (void)n_in; (void)out_size;

    uint16_t *dw1h, *dw2h, *dcw1b, *dcw2b;
    cudaGetSymbolAddress((void**)&dw1h, g_w1h);
    cudaGetSymbolAddress((void**)&dw2h, g_w2h);
    cudaGetSymbolAddress((void**)&dcw1b, g_cw1b);
    cudaGetSymbolAddress((void**)&dcw2b, g_cw2b);

    const int smU = 98304;   // uniform 96 KB -> 2 CTAs/SM
    cudaFuncSetAttribute((const void*)gemm_dual<2,3,0,6,512>,
                         cudaFuncAttributeMaxDynamicSharedMemorySize, smU);
    cudaFuncSetAttribute((const void*)gemm_dual<3,4,1,6,2048>,
                         cudaFuncAttributeMaxDynamicSharedMemorySize, smU);

    // fused LN+LIF1 + weight splits + stat zero (one launch)
    front_union<<<512 + 2564, 256>>>(x, ln_g, ln_b, w1, w2, cw1, cw2);

    // U_b: spike GEMM1 (512 heavy CTAs first) ∪ mix GEMM0 (2048 CTAs)
    gemm_dual<2,3,0,6,512><<<2560, 256, smU>>>(dcw1b, cb1, dw1h, b1);

    // threshold-critical BN1 (proven deterministic path) + LIF2
    bn_slab1<<<256, 256>>>();
    bn_reduce1<<<1, 256>>>();
    lif2_kernel<<<128, 256>>>(bn1g, bn1b);

    // U_c: spike GEMM2 (2048 heavy CTAs first) ∪ mix GEMM1 (2048 CTAs)
    gemm_dual<3,4,1,6,2048><<<4096, 256, smU>>>(dcw2b, cb2, dw2h, b2);

    // final: out = x + mix + BN2(y2)
    final_kernel<<<dim3(B_, C_ / 32, D_ / 32), dim3(32, 8)>>>(out, x, bn2g, bn2b);
}

// round 17
// speedup vs baseline: 1.1713x; 1.1713x over previous
#include <cuda_runtime.h>
#include <cuda_fp16.h>
#include <cuda_bf16.h>
#include <cstdint>

#define B_ 128
#define C_ 1024
#define D_ 256
#define ROWS (B_*C_)
#define CB (C_*B_)

// ---------------- scratch ----------------
__device__ __align__(256) __half g_xn[ROWS*D_];
__device__ __align__(256) __half g_h [ROWS*D_];
__device__ __align__(256) __half g_mix[ROWS*D_];           // mix delta (no x), fp16
__device__ __align__(256) __nv_bfloat16 g_s1t[D_*B_*C_];   // spikes1 [t][b][c]
__device__ __align__(256) __nv_bfloat16 g_s2t[D_*B_*D_];   // spikes2 [t][b][o]
__device__ float g_y1 [D_*B_*D_];                          // fp32 (threshold-critical)
__device__ __align__(256) __half g_y2h[D_*B_*C_];          // fp16 (output-linear)
__device__ float g_pS[D_*D_], g_pQ[D_*D_];                 // BN1 two-stage partials
__device__ float g_S2[C_], g_Q2[C_];                       // BN2 fused stats
__device__ float g_mu1[D_], g_rs1[D_];
// pre-split weight planes (16-bit)
__device__ __align__(256) uint16_t g_w1h [D_*D_];
__device__ __align__(256) uint16_t g_w2h [D_*D_];
__device__ __align__(256) uint16_t g_cw1b[3*D_*C_];        // bf16, 3 planes (threshold-critical)
__device__ __align__(256) uint16_t g_cw2b[2*C_*D_];        // bf16, 2 planes

// ---------------- helpers ----------------
__device__ __forceinline__ uint32_t smem_u32(const void* p) {
    uint32_t a;
    asm("{ .reg .u64 t; cvta.to.shared.u64 t, %1; cvt.u32.u64 %0, t; }" : "=r"(a) : "l"(p));
    return a;
}
__device__ __forceinline__ void ldm4(uint32_t* r, uint32_t a) {
    asm volatile("ldmatrix.sync.aligned.m8n8.x4.shared.b16 {%0,%1,%2,%3}, [%4];"
        : "=r"(r[0]), "=r"(r[1]), "=r"(r[2]), "=r"(r[3]) : "r"(a));
}
template<bool BF>
__device__ __forceinline__ void mma16816(float* c, const uint32_t* a, const uint32_t* b) {
    if (BF)
        asm volatile("mma.sync.aligned.m16n8k16.row.col.f32.bf16.bf16.f32 "
            "{%0,%1,%2,%3},{%4,%5,%6,%7},{%8,%9},{%0,%1,%2,%3};"
            : "+f"(c[0]), "+f"(c[1]), "+f"(c[2]), "+f"(c[3])
            : "r"(a[0]), "r"(a[1]), "r"(a[2]), "r"(a[3]), "r"(b[0]), "r"(b[1]));
    else
        asm volatile("mma.sync.aligned.m16n8k16.row.col.f32.f16.f16.f32 "
            "{%0,%1,%2,%3},{%4,%5,%6,%7},{%8,%9},{%0,%1,%2,%3};"
            : "+f"(c[0]), "+f"(c[1]), "+f"(c[2]), "+f"(c[3])
            : "r"(a[0]), "r"(a[1]), "r"(a[2]), "r"(a[3]), "r"(b[0]), "r"(b[1]));
}
__device__ __forceinline__ int swz(int o) { return o ^ ((o >> 3) & 0x70); }
__device__ __forceinline__ void cpa16(uint32_t s, const void* g) {
    asm volatile("cp.async.cg.shared.global [%0], [%1], 16;" :: "r"(s), "l"(g));
}
#define CP_COMMIT() asm volatile("cp.async.commit_group;" ::: "memory")
#define CP_WAIT(n)  asm volatile("cp.async.wait_group %0;" :: "n"(n) : "memory")

// ---------------- GEMM core ----------------
// ID 0 (f16):  g_xn  @ w1(1 plane)  + b1, relu -> g_h (half)
// ID 1 (f16):  g_h   @ w2(1 plane)  + b2      -> g_mix (half, NO x add)
// ID 2 (bf16): s1t[z] @ cw1(3 planes) + cb1 -> g_y1[z] fp32   [stats via two-stage kernels]
// ID 3 (bf16): s2t[z] @ cw2(2 planes) + cb2 -> g_y2h[z] fp16 + fused BN2 stats (from fp32 accs)
template<int ID, int S>
__device__ __forceinline__ void gemm_core(
    int m0, int n0, int z,
    const uint16_t* __restrict__ Bw, const float* __restrict__ bias, uint8_t* smp)
{
    constexpr bool BF  = (ID >= 2);
    constexpr int K    = (ID == 2) ? 1024 : 256;
    constexpr int NBS  = (ID < 2) ? 1 : (ID == 2) ? 3 : 2;
    constexpr int NPLK = (ID < 2) ? D_*D_ : (ID == 2) ? D_*C_ : C_*D_;
    constexpr int NC   = K / 32;
    constexpr int PL   = 8192;
    constexpr int STG  = (1 + NBS) * PL;
    const uint32_t sbase = smem_u32(smp);

    const int tid = threadIdx.x, lane = tid & 31, wid = tid >> 5;
    const int wm = wid >> 1, wn = wid & 1;
    const int lr = lane & 15, lc = (lane >> 4) << 4;

    const uint16_t* A =
        (ID == 0) ? (const uint16_t*)g_xn + (size_t)m0 * K :
        (ID == 1) ? (const uint16_t*)g_h  + (size_t)m0 * K :
        (ID == 2) ? (const uint16_t*)g_s1t + (size_t)z * (B_ * C_) :
                    (const uint16_t*)g_s2t + (size_t)z * (B_ * D_);

    const int sr = tid >> 1;
    const int sc = (tid & 1) * 16;
    const int raw = sr * 64 + sc * 2;
    const int o0 = swz(raw), o1 = swz(raw + 16);
    float acc[2][8][4] = {};

    auto ISSUE = [&](int ch) {
        const uint32_t st = sbase + (ch % S) * STG;
        const uint16_t* ap = A + (size_t)sr * K + ch * 32 + sc;
        cpa16(st + o0, ap);
        cpa16(st + o1, ap + 8);
        #pragma unroll
        for (int s = 0; s < NBS; s++) {
            const uint16_t* bp = Bw + (size_t)s * NPLK + (size_t)(n0 + sr) * K + ch * 32 + sc;
            cpa16(st + (1 + s) * PL + o0, bp);
            cpa16(st + (1 + s) * PL + o1, bp + 8);
        }
    };
    auto MMA = [&](int buf) {
        const uint32_t bs = sbase + buf * STG;
        #pragma unroll
        for (int ks = 0; ks < 2; ks++) {
            uint32_t a[2][4];
            #pragma unroll
            for (int mi = 0; mi < 2; mi++) {
                int r = (wm * 32 + mi * 16 + lr) * 64 + ks * 32 + lc;
                ldm4(a[mi], bs + swz(r));
            }
            #pragma unroll
            for (int p = 0; p < NBS; p++) {
                const uint32_t Bb = bs + (1 + p) * PL;
                uint32_t bq[8][2];
                #pragma unroll
                for (int nj = 0; nj < 4; nj++) {
                    int r = (wn * 64 + nj * 16 + lr) * 64 + ks * 32 + lc;
                    uint32_t tq[4];
                    ldm4(tq, Bb + swz(r));
                    bq[2*nj][0] = tq[0];   bq[2*nj][1] = tq[2];
                    bq[2*nj+1][0] = tq[1]; bq[2*nj+1][1] = tq[3];
                }
                #pragma unroll
                for (int mi = 0; mi < 2; mi++)
                    #pragma unroll
                    for (int nj = 0; nj < 8; nj++)
                        mma16816<BF>(acc[mi][nj], a[mi], bq[nj]);
            }
        }
    };

    #pragma unroll
    for (int s = 0; s < S - 1; s++) { ISSUE(s); CP_COMMIT(); }
    for (int i = 0; i < NC; i++) {
        CP_WAIT(S - 2);
        __syncthreads();
        int nx = i + S - 1;
        if (nx < NC) ISSUE(nx);
        CP_COMMIT();
        MMA(i % S);
    }

    const int er = lane >> 2, ec = (lane & 3) * 2;
    #pragma unroll
    for (int mi = 0; mi < 2; mi++) {
        #pragma unroll
        for (int nj = 0; nj < 8; nj++) {
            float* c = acc[mi][nj];
            int m = m0 + wm * 32 + mi * 16 + er;
            int n = n0 + wn * 64 + nj * 8 + ec;
            float b0 = __ldg(bias + n), b1 = __ldg(bias + n + 1);
            if (ID == 0) {
                *(__half2*)(g_h + (size_t)m * 256 + n) =
                    __floats2half2_rn(fmaxf(c[0] + b0, 0.f), fmaxf(c[1] + b1, 0.f));
                *(__half2*)(g_h + (size_t)(m + 8) * 256 + n) =
                    __floats2half2_rn(fmaxf(c[2] + b0, 0.f), fmaxf(c[3] + b1, 0.f));
            } else if (ID == 1) {
                *(__half2*)(g_mix + (size_t)m * 256 + n) =
                    __floats2half2_rn(c[0] + b0, c[1] + b1);
                *(__half2*)(g_mix + (size_t)(m + 8) * 256 + n) =
                    __floats2half2_rn(c[2] + b0, c[3] + b1);
            } else if (ID == 2) {
                float* yb = g_y1 + (size_t)z * (B_ * 256);
                *(float2*)(yb + (size_t)m * 256 + n) = make_float2(c[0] + b0, c[1] + b1);
                *(float2*)(yb + (size_t)(m + 8) * 256 + n) = make_float2(c[2] + b0, c[3] + b1);
            } else {
                float y00 = c[0] + b0, y01 = c[1] + b1;
                float y10 = c[2] + b0, y11 = c[3] + b1;
                __half* yb = g_y2h + (size_t)z * (B_ * 1024);
                *(__half2*)(yb + (size_t)m * 1024 + n) = __floats2half2_rn(y00, y01);
                *(__half2*)(yb + (size_t)(m + 8) * 1024 + n) = __floats2half2_rn(y10, y11);
                float a0 = y00 + y10, a1 = y01 + y11;
                float q0 = y00 * y00 + y10 * y10, q1 = y01 * y01 + y11 * y11;
                #pragma unroll
                for (int off = 4; off < 32; off <<= 1) {
                    a0 += __shfl_xor_sync(0xffffffffu, a0, off);
                    a1 += __shfl_xor_sync(0xffffffffu, a1, off);
                    q0 += __shfl_xor_sync(0xffffffffu, q0, off);
                    q1 += __shfl_xor_sync(0xffffffffu, q1, off);
                }
                if (er == 0) {
                    atomicAdd(g_S2 + n, a0);
                    atomicAdd(g_S2 + n + 1, a1);
                    atomicAdd(g_Q2 + n, q0);
                    atomicAdd(g_Q2 + n + 1, q1);
                }
            }
        }
    }
}

// ---------------- dual GEMM launch (grid union, heavy spike side first) ----------------
template<int IDA, int SA, int IDB, int SB, int NBA>
__global__ void __launch_bounds__(256, 2)
gemm_dual(const uint16_t* __restrict__ BwA, const float* __restrict__ biasA,
          const uint16_t* __restrict__ BwB, const float* __restrict__ biasB)
{
    extern __shared__ uint8_t smp[];
    int lb = blockIdx.x;
    if (lb < NBA) {
        int by = (IDA == 2) ? (lb & 1) : (lb & 7);
        int bz = (IDA == 2) ? (lb >> 1) : (lb >> 3);
        gemm_core<IDA, SA>(0, by * 128, bz, BwA, biasA, smp);
    } else {
        int l2 = lb - NBA;
        gemm_core<IDB, SB>((l2 & 1023) * 128, (l2 >> 10) * 128, 0, BwB, biasB, smp);
    }
}

// ---------------- front union: LIF1 (512) + LN warp-per-row (16384) + prep (2564) ----------------
__device__ __forceinline__ void split_body(const float* src, uint16_t* dst, int n, int i, bool bf, int nbs) {
    if (i >= n) return;
    float v = src[i];
    for (int s = 0; s < nbs; s++) {
        if (bf) {
            __nv_bfloat16 b = __float2bfloat16(v);
            dst[s * n + i] = __bfloat16_as_ushort(b);
            v -= __bfloat162float(b);
        } else {
            __half b = __float2half_rn(v);
            dst[s * n + i] = __half_as_ushort(b);
            v -= __half2float(b);
        }
    }
}
__global__ void front_union(const float* __restrict__ x,
                            const float* __restrict__ gam, const float* __restrict__ bet,
                            const float* w1, const float* w2,
                            const float* cw1, const float* cw2) {
    if (blockIdx.x < 512) {
        // LIF 1: x[b][c][t] -> s1t[t][b][c] bf16 (proven R15 body)
        int tid = blockIdx.x * 256 + threadIdx.x;
        int b = tid >> 10, c = tid & 1023;
        const float4* xr = (const float4*)(x + ((size_t)b * C_ + c) * D_);
        __nv_bfloat16* sp = g_s1t + (size_t)b * C_ + c;
        float v = 0.0f;
        for (int q = 0; q < 64; q++) {
            float4 xv = xr[q];
            float xa[4] = {xv.x, xv.y, xv.z, xv.w};
            #pragma unroll
            for (int j = 0; j < 4; j++) {
                v = v + (xa[j] - v) * 0.5f;
                float s = (v >= 1.0f) ? 1.0f : 0.0f;
                sp[(size_t)(q * 4 + j) * CB] = __float2bfloat16(s);
                if (v >= 1.0f) v = 0.0f;
            }
        }
    } else if (blockIdx.x < 512 + 16384) {
        // LayerNorm -> fp16 g_xn (1 warp/row, coalesced; proven R15 body)
        int gw = ((blockIdx.x - 512) * 256 + threadIdx.x) >> 5;
        int lane = threadIdx.x & 31;
        const float4* xr = (const float4*)(x + (size_t)gw * D_);
        float4 v0 = xr[lane], v1 = xr[lane + 32];
        float s = v0.x+v0.y+v0.z+v0.w + v1.x+v1.y+v1.z+v1.w;
        float q = v0.x*v0.x+v0.y*v0.y+v0.z*v0.z+v0.w*v0.w + v1.x*v1.x+v1.y*v1.y+v1.z*v1.z+v1.w*v1.w;
        #pragma unroll
        for (int o = 16; o; o >>= 1) {
            s += __shfl_xor_sync(0xffffffffu, s, o);
            q += __shfl_xor_sync(0xffffffffu, q, o);
        }
        float mu = s * (1.0f / D_);
        float rs = rsqrtf(q * (1.0f / D_) - mu * mu + 1e-5f);
        const float4* gg = (const float4*)gam;
        const float4* bb = (const float4*)bet;
        float4 g0 = gg[lane], g1 = gg[lane + 32], b0 = bb[lane], b1 = bb[lane + 32];
        __half2 h0 = __floats2half2_rn((v0.x-mu)*rs*g0.x+b0.x, (v0.y-mu)*rs*g0.y+b0.y);
        __half2 h1 = __floats2half2_rn((v0.z-mu)*rs*g0.z+b0.z, (v0.w-mu)*rs*g0.w+b0.w);
        __half2 h2 = __floats2half2_rn((v1.x-mu)*rs*g1.x+b1.x, (v1.y-mu)*rs*g1.y+b1.y);
        __half2 h3 = __floats2half2_rn((v1.z-mu)*rs*g1.z+b1.z, (v1.w-mu)*rs*g1.w+b1.w);
        __half2* base = (__half2*)(g_xn + (size_t)gw * D_);
        base[2*lane] = h0; base[2*lane+1] = h1;
        base[2*(lane+32)] = h2; base[2*(lane+32)+1] = h3;
    } else {
        int bx = blockIdx.x - (512 + 16384), tid = threadIdx.x;
        if (bx < 256)        split_body(w1,  g_w1h,  D_*D_, bx * 256 + tid, false, 1);
        else if (bx < 512)   split_body(w2,  g_w2h,  D_*D_, (bx - 256) * 256 + tid, false, 1);
        else if (bx < 1536)  split_body(cw1, g_cw1b, D_*C_, (bx - 512) * 256 + tid, true, 3);
        else if (bx < 2560)  split_body(cw2, g_cw2b, C_*D_, (bx - 1536) * 256 + tid, true, 2);
        else {
            int i = (bx - 2560) * 256 + tid;
            if (i < C_) { g_S2[i] = 0.f; g_Q2[i] = 0.f; }
        }
    }
}

// ---------------- BN1 two-stage stats (proven, threshold-critical) ----------------
__global__ void bn_slab1() {
    int t = blockIdx.x, tid = threadIdx.x;
    float s = 0.0f, q = 0.0f;
    const float* base = g_y1 + (size_t)t * 128 * 256;
    for (int b = 0; b < 128; b++) {
        float v = base[(size_t)b * 256 + tid];
        s += v; q += v * v;
    }
    g_pS[(size_t)t * 256 + tid] = s;
    g_pQ[(size_t)t * 256 + tid] = q;
}
// grid=8, block=32: same one-thread-per-channel serial order (bit-identical mu1/rs1)
__global__ void bn_reduce1() {
    int c = blockIdx.x * 32 + threadIdx.x;
    float S = 0.0f, Q = 0.0f;
    for (int t = 0; t < 256; t++) {
        S += g_pS[(size_t)t * 256 + c];
        Q += g_pQ[(size_t)t * 256 + c];
    }
    float mean = S * (1.0f / 32768.0f);
    float var = Q * (1.0f / 32768.0f) - mean * mean;
    g_mu1[c] = mean;
    g_rs1[c] = rsqrtf(var + 1e-5f);
}

// ---------------- BN1 + LIF 2 ----------------
__global__ void lif2_kernel(const float* __restrict__ gam, const float* __restrict__ bet) {
    int tid = blockIdx.x * blockDim.x + threadIdx.x;
    int b = tid >> 8, o = tid & 255;
    float mu = g_mu1[o], rs = g_rs1[o], ga = gam[o], be = bet[o];
    const float* yp = g_y1 + (size_t)b * 256 + o;
    __nv_bfloat16* sp = g_s2t + (size_t)b * 256 + o;
    float v = 0.0f;
    for (int t = 0; t < D_; t++) {
        float yn = ((yp[(size_t)t * 32768] - mu) * rs) * ga + be;
        v = v + (yn - v) * 0.5f;
        float s = (v >= 1.0f) ? 1.0f : 0.0f;
        sp[(size_t)t * 32768] = __float2bfloat16(s);
        if (v >= 1.0f) v = 0.0f;
    }
}

// ---------------- final: out = x + mix + BN2(y2) ----------------
__global__ void final_kernel(float* __restrict__ out, const float* __restrict__ x,
                             const float* __restrict__ gam, const float* __restrict__ bet) {
    __shared__ float tile[32][33];
    int b = blockIdx.x;
    int c0 = blockIdx.y << 5, t0 = blockIdx.z << 5;
    #pragma unroll
    for (int i = 0; i < 4; i++) {
        int t = t0 + threadIdx.y + i * 8;
        tile[threadIdx.y + i * 8][threadIdx.x] =
            __half2float(g_y2h[(size_t)t * (B_ * 1024) + (size_t)b * 1024 + c0 + threadIdx.x]);
    }
    __syncthreads();
    #pragma unroll
    for (int i = 0; i < 4; i++) {
        int c = c0 + threadIdx.y + i * 8;
        float mu = g_S2[c] * (1.0f / 32768.0f);
        float rs = rsqrtf(g_Q2[c] * (1.0f / 32768.0f) - mu * mu + 1e-5f);
        float ga = __ldg(gam + c), be = __ldg(bet + c);
        size_t o = (size_t)b * (C_ * D_) + (size_t)c * D_ + t0 + threadIdx.x;
        float mixv = __half2float(g_mix[o]);
        out[o] = x[o] + mixv + (tile[threadIdx.x][threadIdx.y + i * 8] - mu) * rs * ga + be;
    }
}

// ---------------- launch ----------------
extern "C" void kernel_launch(void* const* d_in, const int* in_sizes, int n_in,
                              void* d_out, int out_size) {
    const float* x    = (const float*)d_in[0];
    const float* ln_g = (const float*)d_in[1];
    const float* ln_b = (const float*)d_in[2];
    const float* w1   = (const float*)d_in[3];
    const float* b1   = (const float*)d_in[4];
    const float* w2   = (const float*)d_in[5];
    const float* b2   = (const float*)d_in[6];
    const float* cw1  = (const float*)d_in[7];
    const float* cb1  = (const float*)d_in[8];
    const float* bn1g = (const float*)d_in[9];
    const float* bn1b = (const float*)d_in[10];
    const float* cw2  = (const float*)d_in[11];
    const float* cb2  = (const float*)d_in[12];
    const float* bn2g = (const float*)d_in[13];
    const float* bn2b = (const float*)d_in[14];
    float* out = (float*)d_out;
    (void)in_sizes; (void)n_in; (void)out_size;

    uint16_t *dw1h, *dw2h, *dcw1b, *dcw2b;
    cudaGetSymbolAddress((void**)&dw1h, g_w1h);
    cudaGetSymbolAddress((void**)&dw2h, g_w2h);
    cudaGetSymbolAddress((void**)&dcw1b, g_cw1b);
    cudaGetSymbolAddress((void**)&dcw2b, g_cw2b);

    const int smU = 98304;   // uniform 96 KB -> 2 CTAs/SM
    cudaFuncSetAttribute((const void*)gemm_dual<2,3,0,6,512>,
                         cudaFuncAttributeMaxDynamicSharedMemorySize, smU);
    cudaFuncSetAttribute((const void*)gemm_dual<3,4,1,6,2048>,
                         cudaFuncAttributeMaxDynamicSharedMemorySize, smU);

    // LIF1 + LN + weight splits + stat zero (one launch; all coalesced bodies)
    front_union<<<512 + 16384 + 2564, 256>>>(x, ln_g, ln_b, w1, w2, cw1, cw2);

    // U_b: spike GEMM1 (512 heavy CTAs first) ∪ mix GEMM0 (2048 CTAs)
    gemm_dual<2,3,0,6,512><<<2560, 256, smU>>>(dcw1b, cb1, dw1h, b1);

    // threshold-critical BN1 (deterministic order preserved) + LIF2
    bn_slab1<<<256, 256>>>();
    bn_reduce1<<<8, 32>>>();
    lif2_kernel<<<128, 256>>>(bn1g, bn1b);

    // U_c: spike GEMM2 (2048 heavy CTAs first) ∪ mix GEMM1 (2048 CTAs)
    gemm_dual<3,4,1,6,2048><<<4096, 256, smU>>>(dcw2b, cb2, dw2h, b2);

    // final: out = x + mix + BN2(y2)
    final_kernel<<<dim3(B_, C_ / 32, D_ / 32), dim3(32, 8)>>>(out, x, bn2g, bn2b);
}